// round 1
// baseline (speedup 1.0000x reference)
#include <cuda_runtime.h>

// ---------------------------------------------------------------------------
// Quanvolution2D: 9-qubit statevector simulation per 3x3 patch.
//
// Circuit per patch p (9 angles), weights w (2,9):
//   RX(p_i) ; RX(w0_i)          -> merged: product state with theta_i = p_i+w0_i
//   CNOT ring (0,1)...(8,0)     -> GF(2)-linear basis permutation P (index map)
//   RX(w1_i)                    -> butterflies with XOR masks P^-1(e_q)
//   CNOT ring                   -> index map becomes P^2
//   <Z_i> i=0..3                -> sign = parity(n & row_i(P^2))
//
// One warp per (b, y, x); 512 complex amps = 16 (re,im) pairs per lane,
// fully register resident. No shared memory, no atomics (deterministic).
// ---------------------------------------------------------------------------

namespace {

constexpr int NQ = 9;

// Forward basis permutation of one CNOT ring: CNOT(0,1), CNOT(1,2), ..., CNOT(8,0)
__host__ __device__ constexpr int permP(int n) {
    int b[NQ] = {};
    for (int i = 0; i < NQ; ++i) b[i] = (n >> i) & 1;
    for (int i = 0; i < NQ; ++i) b[(i + 1) % NQ] ^= b[i];   // target ^= control
    int r = 0;
    for (int i = 0; i < NQ; ++i) r |= b[i] << i;
    return r;
}

// Inverse permutation lookup (P is a bijection on 9-bit indices)
__host__ __device__ constexpr int invP(int y) {
    for (int n = 0; n < 512; ++n)
        if (permP(n) == y) return n;
    return 0;
}

// Row mask of P^2: bit i of P(P(n)) == parity(n & rowPP(i))  (P is GF(2)-linear)
__host__ __device__ constexpr int rowPP(int i) {
    int r = 0;
    for (int j = 0; j < NQ; ++j) {
        int y = permP(permP(1 << j));
        r |= ((y >> i) & 1) << j;
    }
    return r;
}

constexpr unsigned FULL = 0xffffffffu;

// In-lane butterfly: partner element index t ^ LOC (LOC < 16, lane part 0).
template <int LOC>
__device__ __forceinline__ void rx_inlane(float c, float s, float* ar, float* ai) {
#pragma unroll
    for (int t = 0; t < 16; ++t) {
        const int p = t ^ LOC;
        if (t < p) {
            float a0r = ar[t], a0i = ai[t], a1r = ar[p], a1i = ai[p];
            ar[t] = c * a0r + s * a1i;
            ai[t] = c * a0i - s * a1r;
            ar[p] = c * a1r + s * a0i;
            ai[p] = c * a1i - s * a0r;
        }
    }
}

// Cross-lane butterfly, same element index: partner lane = lane ^ LX.
template <int LX>
__device__ __forceinline__ void rx_xlane(float c, float s, float* ar, float* ai) {
#pragma unroll
    for (int t = 0; t < 16; ++t) {
        float pr = __shfl_xor_sync(FULL, ar[t], LX);
        float pi = __shfl_xor_sync(FULL, ai[t], LX);
        ar[t] = c * ar[t] + s * pi;
        ai[t] = c * ai[t] - s * pr;
    }
}

// Cross-lane + cross-element butterfly: partner = (lane ^ LX, t ^ LOC).
template <int LX, int LOC>
__device__ __forceinline__ void rx_mixed(float c, float s, float* ar, float* ai) {
#pragma unroll
    for (int t = 0; t < 16; ++t) {
        const int p = t ^ LOC;
        if (t < p) {
            // read all olds (own + partner) before any write; pairs are disjoint
            float prt = __shfl_xor_sync(FULL, ar[p], LX);
            float pit = __shfl_xor_sync(FULL, ai[p], LX);
            float prp = __shfl_xor_sync(FULL, ar[t], LX);
            float pip = __shfl_xor_sync(FULL, ai[t], LX);
            ar[t] = c * ar[t] + s * pit;
            ai[t] = c * ai[t] - s * prt;
            ar[p] = c * ar[p] + s * pip;
            ai[p] = c * ai[p] - s * prp;
        }
    }
}

template <int M>
__device__ __forceinline__ void rx_gate(float c, float s, float* ar, float* ai) {
    constexpr int LX = M >> 4;
    constexpr int LOC = M & 15;
    if constexpr (LX == 0)       rx_inlane<LOC>(c, s, ar, ai);
    else if constexpr (LOC == 0) rx_xlane<LX>(c, s, ar, ai);
    else                         rx_mixed<LX, LOC>(c, s, ar, ai);
}

__global__ void __launch_bounds__(128)
quanv_kernel(const float* __restrict__ x, const float* __restrict__ qw,
             float* __restrict__ out) {
    constexpr int B = 4, C = 3, H = 28, W = 28, HO = 26, WO = 26;

    const int gw = (blockIdx.x * blockDim.x + threadIdx.x) >> 5;  // warp id = patch pos
    const int lane = threadIdx.x & 31;
    if (gw >= B * HO * WO) return;  // grid is exact; kept for safety (whole warp)

    const int xo = gw % WO;
    const int yo = (gw / WO) % HO;
    const int b  = gw / (WO * HO);

    // Layer-2 half-angle sincos: lane q computes qubit q, broadcast on demand.
    float cv2, sv2;
    {
        float a2 = (lane < NQ) ? 0.5f * qw[NQ + lane] : 0.f;
        sincosf(a2, &sv2, &cv2);
    }

    float acc0 = 0.f, acc1 = 0.f, acc2 = 0.f, acc3 = 0.f;

#pragma unroll 1
    for (int ch = 0; ch < C; ++ch) {
        const float* xp = x + ((b * C + ch) * H + yo) * W + xo;

        // theta_q = p_q + w0_q ; lane q computes sincos(theta_q/2), rest idle-compute 0.
        float cv, sv;
        {
            float a = 0.f;
            if (lane < NQ) {
                const int dy = lane / 3, dx = lane % 3;
                a = 0.5f * (xp[dy * W + dx] + qw[lane]);
            }
            sincosf(a, &sv, &cv);
        }

        // ---- Build merged-RX product state: physical index n = (lane<<4)|t ----
        float hi = 1.f;
#pragma unroll
        for (int q = 4; q < NQ; ++q) {
            float cq = __shfl_sync(FULL, cv, q);
            float sq = __shfl_sync(FULL, sv, q);
            hi *= ((lane >> (q - 4)) & 1) ? sq : cq;
        }

        float lo[16];
        lo[0] = 1.f;
#pragma unroll
        for (int q = 0; q < 4; ++q) {
            float cq = __shfl_sync(FULL, cv, q);
            float sq = __shfl_sync(FULL, sv, q);
#pragma unroll
            for (int t = 15; t >= 0; --t) {
                if (t < (1 << q)) {
                    lo[t + (1 << q)] = lo[t] * sq;
                    lo[t] = lo[t] * cq;
                }
            }
        }

        float ar[16], ai[16];
        const int popl = __popc(lane);
#pragma unroll
        for (int t = 0; t < 16; ++t) {
            float m = hi * lo[t];
            int ph = (popl + __popc(t)) & 3;   // (-i)^popcount phase
            ar[t] = (ph == 0) ? m : ((ph == 2) ? -m : 0.f);
            ai[t] = (ph == 1) ? -m : ((ph == 3) ? m : 0.f);
        }

        // ---- RX(w1) layer in permuted index space (masks = P^-1(e_q)) ----
        {
            float c, s;
#define RXQ(Q)                                                     \
            c = __shfl_sync(FULL, cv2, Q);                         \
            s = __shfl_sync(FULL, sv2, Q);                         \
            rx_gate<invP(1 << Q)>(c, s, ar, ai);
            RXQ(0) RXQ(1) RXQ(2) RXQ(3) RXQ(4) RXQ(5) RXQ(6) RXQ(7) RXQ(8)
#undef RXQ
        }

        // ---- Measurement: <Z_i> = sum_n |A[n]|^2 * (1 - 2*parity(n & rowPP(i))) ----
        constexpr int R0 = rowPP(0), R1 = rowPP(1), R2 = rowPP(2), R3 = rowPP(3);
        float zt0 = 0.f, zt1 = 0.f, zt2 = 0.f, zt3 = 0.f;
#pragma unroll
        for (int t = 0; t < 16; ++t) {
            float p = ar[t] * ar[t] + ai[t] * ai[t];
            zt0 += (__popc(t & (R0 & 15)) & 1) ? -p : p;
            zt1 += (__popc(t & (R1 & 15)) & 1) ? -p : p;
            zt2 += (__popc(t & (R2 & 15)) & 1) ? -p : p;
            zt3 += (__popc(t & (R3 & 15)) & 1) ? -p : p;
        }
        acc0 += (__popc(lane & (R0 >> 4)) & 1) ? -zt0 : zt0;
        acc1 += (__popc(lane & (R1 >> 4)) & 1) ? -zt1 : zt1;
        acc2 += (__popc(lane & (R2 >> 4)) & 1) ? -zt2 : zt2;
        acc3 += (__popc(lane & (R3 >> 4)) & 1) ? -zt3 : zt3;
    }

    // ---- Warp reduction over 32 lanes (channel sums already folded in) ----
#pragma unroll
    for (int o = 16; o >= 1; o >>= 1) {
        acc0 += __shfl_xor_sync(FULL, acc0, o);
        acc1 += __shfl_xor_sync(FULL, acc1, o);
        acc2 += __shfl_xor_sync(FULL, acc2, o);
        acc3 += __shfl_xor_sync(FULL, acc3, o);
    }

    if (lane == 0) {
        const float inv3 = 1.f / 3.f;
        const int base = (b * 4 * HO + yo) * WO + xo;
        out[base + 0 * HO * WO] = acc0 * inv3;
        out[base + 1 * HO * WO] = acc1 * inv3;
        out[base + 2 * HO * WO] = acc2 * inv3;
        out[base + 3 * HO * WO] = acc3 * inv3;
    }
}

}  // namespace

extern "C" void kernel_launch(void* const* d_in, const int* in_sizes, int n_in,
                              void* d_out, int out_size) {
    const float* x  = (const float*)d_in[0];   // (4,3,28,28) float32
    const float* qw = (const float*)d_in[1];   // (2,9) float32
    float* out = (float*)d_out;                // (4,4,26,26) float32

    // 4*26*26 = 2704 warps, 4 warps/block -> exactly 676 blocks
    quanv_kernel<<<676, 128>>>(x, qw, out);
}

// round 2
// speedup vs baseline: 1.0860x; 1.0860x over previous
#include <cuda_runtime.h>

// ---------------------------------------------------------------------------
// Quanvolution2D: 9-qubit statevector simulation per 3x3 patch.
//
// Circuit per patch p (9 angles), weights w (2,9):
//   RX(p_i) ; RX(w0_i)          -> merged: product state with theta_i = p_i+w0_i
//   CNOT ring (0,1)...(8,0)     -> GF(2)-linear basis permutation P (index map)
//   RX(w1_i)                    -> butterflies with XOR masks P^-1(e_q)
//   CNOT ring                   -> index map becomes P^2
//   <Z_i> i=0..3                -> sign = parity(n & row_i(P^2))
//
// R2: one block per patch, 3 warps = 3 channels in parallel (3x warp-level
// parallelism vs R1's serial channel loop). Deterministic fixed-order channel
// reduction via shared memory. __sincosf fast trig.
// ---------------------------------------------------------------------------

namespace {

constexpr int NQ = 9;

// Forward basis permutation of one CNOT ring: CNOT(0,1), CNOT(1,2), ..., CNOT(8,0)
__host__ __device__ constexpr int permP(int n) {
    int b[NQ] = {};
    for (int i = 0; i < NQ; ++i) b[i] = (n >> i) & 1;
    for (int i = 0; i < NQ; ++i) b[(i + 1) % NQ] ^= b[i];   // target ^= control
    int r = 0;
    for (int i = 0; i < NQ; ++i) r |= b[i] << i;
    return r;
}

// Inverse permutation lookup (P is a bijection on 9-bit indices)
__host__ __device__ constexpr int invP(int y) {
    for (int n = 0; n < 512; ++n)
        if (permP(n) == y) return n;
    return 0;
}

// Row mask of P^2: bit i of P(P(n)) == parity(n & rowPP(i))  (P is GF(2)-linear)
__host__ __device__ constexpr int rowPP(int i) {
    int r = 0;
    for (int j = 0; j < NQ; ++j) {
        int y = permP(permP(1 << j));
        r |= ((y >> i) & 1) << j;
    }
    return r;
}

constexpr unsigned FULL = 0xffffffffu;

// In-lane butterfly: partner element index t ^ LOC (LOC < 16, lane part 0).
template <int LOC>
__device__ __forceinline__ void rx_inlane(float c, float s, float* ar, float* ai) {
#pragma unroll
    for (int t = 0; t < 16; ++t) {
        const int p = t ^ LOC;
        if (t < p) {
            float a0r = ar[t], a0i = ai[t], a1r = ar[p], a1i = ai[p];
            ar[t] = c * a0r + s * a1i;
            ai[t] = c * a0i - s * a1r;
            ar[p] = c * a1r + s * a0i;
            ai[p] = c * a1i - s * a0r;
        }
    }
}

// Cross-lane butterfly, same element index: partner lane = lane ^ LX.
template <int LX>
__device__ __forceinline__ void rx_xlane(float c, float s, float* ar, float* ai) {
#pragma unroll
    for (int t = 0; t < 16; ++t) {
        float pr = __shfl_xor_sync(FULL, ar[t], LX);
        float pi = __shfl_xor_sync(FULL, ai[t], LX);
        ar[t] = c * ar[t] + s * pi;
        ai[t] = c * ai[t] - s * pr;
    }
}

// Cross-lane + cross-element butterfly: partner = (lane ^ LX, t ^ LOC).
template <int LX, int LOC>
__device__ __forceinline__ void rx_mixed(float c, float s, float* ar, float* ai) {
#pragma unroll
    for (int t = 0; t < 16; ++t) {
        const int p = t ^ LOC;
        if (t < p) {
            // read all olds (own + partner) before any write; pairs are disjoint
            float prt = __shfl_xor_sync(FULL, ar[p], LX);
            float pit = __shfl_xor_sync(FULL, ai[p], LX);
            float prp = __shfl_xor_sync(FULL, ar[t], LX);
            float pip = __shfl_xor_sync(FULL, ai[t], LX);
            ar[t] = c * ar[t] + s * pit;
            ai[t] = c * ai[t] - s * prt;
            ar[p] = c * ar[p] + s * pip;
            ai[p] = c * ai[p] - s * prp;
        }
    }
}

template <int M>
__device__ __forceinline__ void rx_gate(float c, float s, float* ar, float* ai) {
    constexpr int LX = M >> 4;
    constexpr int LOC = M & 15;
    if constexpr (LX == 0)       rx_inlane<LOC>(c, s, ar, ai);
    else if constexpr (LOC == 0) rx_xlane<LX>(c, s, ar, ai);
    else                         rx_mixed<LX, LOC>(c, s, ar, ai);
}

__global__ void __launch_bounds__(96)
quanv_kernel(const float* __restrict__ x, const float* __restrict__ qw,
             float* __restrict__ out) {
    constexpr int C = 3, H = 28, W = 28, HO = 26, WO = 26;

    const int gw   = blockIdx.x;              // patch id = (b, yo, xo)
    const int ch   = threadIdx.x >> 5;        // warp -> channel
    const int lane = threadIdx.x & 31;

    const int xo = gw % WO;
    const int yo = (gw / WO) % HO;
    const int b  = gw / (WO * HO);

    __shared__ float red[C][4];

    // Layer-2 half-angle sincos: lane q computes qubit q, broadcast on demand.
    float cv2, sv2;
    {
        float a2 = (lane < NQ) ? 0.5f * qw[NQ + lane] : 0.f;
        __sincosf(a2, &sv2, &cv2);
    }

    const float* xp = x + ((b * C + ch) * H + yo) * W + xo;

    // theta_q = p_q + w0_q ; lane q computes sincos(theta_q/2).
    float cv, sv;
    {
        float a = 0.f;
        if (lane < NQ) {
            const int dy = lane / 3, dx = lane % 3;
            a = 0.5f * (xp[dy * W + dx] + qw[lane]);
        }
        __sincosf(a, &sv, &cv);
    }

    // ---- Build merged-RX product state: physical index n = (lane<<4)|t ----
    float hi = 1.f;
#pragma unroll
    for (int q = 4; q < NQ; ++q) {
        float cq = __shfl_sync(FULL, cv, q);
        float sq = __shfl_sync(FULL, sv, q);
        hi *= ((lane >> (q - 4)) & 1) ? sq : cq;
    }

    float lo[16];
    lo[0] = 1.f;
#pragma unroll
    for (int q = 0; q < 4; ++q) {
        float cq = __shfl_sync(FULL, cv, q);
        float sq = __shfl_sync(FULL, sv, q);
#pragma unroll
        for (int t = 15; t >= 0; --t) {
            if (t < (1 << q)) {
                lo[t + (1 << q)] = lo[t] * sq;
                lo[t] = lo[t] * cq;
            }
        }
    }

    float ar[16], ai[16];
    const int popl = __popc(lane);
#pragma unroll
    for (int t = 0; t < 16; ++t) {
        float m = hi * lo[t];
        int ph = (popl + __popc(t)) & 3;   // (-i)^popcount phase
        ar[t] = (ph == 0) ? m : ((ph == 2) ? -m : 0.f);
        ai[t] = (ph == 1) ? -m : ((ph == 3) ? m : 0.f);
    }

    // ---- RX(w1) layer in permuted index space (masks = P^-1(e_q)) ----
    {
        float c, s;
#define RXQ(Q)                                                 \
        c = __shfl_sync(FULL, cv2, Q);                         \
        s = __shfl_sync(FULL, sv2, Q);                         \
        rx_gate<invP(1 << Q)>(c, s, ar, ai);
        RXQ(0) RXQ(1) RXQ(2) RXQ(3) RXQ(4) RXQ(5) RXQ(6) RXQ(7) RXQ(8)
#undef RXQ
    }

    // ---- Measurement: <Z_i> = sum_n |A[n]|^2 * (1 - 2*parity(n & rowPP(i))) ----
    constexpr int R0 = rowPP(0), R1 = rowPP(1), R2 = rowPP(2), R3 = rowPP(3);
    float zt0 = 0.f, zt1 = 0.f, zt2 = 0.f, zt3 = 0.f;
#pragma unroll
    for (int t = 0; t < 16; ++t) {
        float p = ar[t] * ar[t] + ai[t] * ai[t];
        zt0 += (__popc(t & (R0 & 15)) & 1) ? -p : p;   // compile-time signs
        zt1 += (__popc(t & (R1 & 15)) & 1) ? -p : p;
        zt2 += (__popc(t & (R2 & 15)) & 1) ? -p : p;
        zt3 += (__popc(t & (R3 & 15)) & 1) ? -p : p;
    }
    float acc0 = (__popc(lane & (R0 >> 4)) & 1) ? -zt0 : zt0;
    float acc1 = (__popc(lane & (R1 >> 4)) & 1) ? -zt1 : zt1;
    float acc2 = (__popc(lane & (R2 >> 4)) & 1) ? -zt2 : zt2;
    float acc3 = (__popc(lane & (R3 >> 4)) & 1) ? -zt3 : zt3;

    // ---- Warp reduction over 32 lanes ----
#pragma unroll
    for (int o = 16; o >= 1; o >>= 1) {
        acc0 += __shfl_xor_sync(FULL, acc0, o);
        acc1 += __shfl_xor_sync(FULL, acc1, o);
        acc2 += __shfl_xor_sync(FULL, acc2, o);
        acc3 += __shfl_xor_sync(FULL, acc3, o);
    }

    if (lane == 0) {
        red[ch][0] = acc0;
        red[ch][1] = acc1;
        red[ch][2] = acc2;
        red[ch][3] = acc3;
    }
    __syncthreads();

    // Fixed-order channel mean (deterministic), 4 threads write 4 filters.
    if (threadIdx.x < 4) {
        const int f = threadIdx.x;
        const float inv3 = 1.f / 3.f;
        float v = (red[0][f] + red[1][f] + red[2][f]) * inv3;
        out[((b * 4 + f) * HO + yo) * WO + xo] = v;
    }
}

}  // namespace

extern "C" void kernel_launch(void* const* d_in, const int* in_sizes, int n_in,
                              void* d_out, int out_size) {
    const float* x  = (const float*)d_in[0];   // (4,3,28,28) float32
    const float* qw = (const float*)d_in[1];   // (2,9) float32
    float* out = (float*)d_out;                // (4,4,26,26) float32

    // One block per patch position: 4*26*26 = 2704 blocks, 3 warps each.
    quanv_kernel<<<2704, 96>>>(x, qw, out);
}

// round 3
// speedup vs baseline: 2.7023x; 2.4884x over previous
#include <cuda_runtime.h>

// ---------------------------------------------------------------------------
// Quanvolution2D — closed-form Pauli-algebra evaluation.
//
// Circuit: RX(theta=p+w0) ; ring ; RX(w1) ; ring ; <Z_0..3>
// Equivalent (verified R1/R2 formulation): product state |phi> = (x)RX(theta_j)|0>,
// then V = prod_q exp(-i w1_q/2 X_{M_q}) with M_q = invP(e_q), measure Z_{R_i}
// with R_i = rowPP(i).
//
// Since all X_{M_q} commute:  V^dag Z_R V = prod_{q in A} exp(+i w_q X_{M_q}) Z_R,
// A = {q : |M_q & R| odd}. Expanding and using product-state expectations
//   <Z> = cos(theta), <XZ> = i sin(theta), <X> = 0   (FULL angles),
// only terms with  M_T := XOR_{q in T} M_q  contained in R survive:
//
//   <Z_i> = sum_T sign * prod_{q in T} sin(w1_q) * prod_{q in A\T} cos(w1_q)
//                 * prod_{j in M_T} sin(theta_j) * prod_{j in R\M_T} cos(theta_j)
//
// Only 16 terms total across the 4 filters. ~100 multiplies per circuit
// instead of a 512-amplitude simulation. One thread per patch, 3 channels
// serial. No shuffles, no smem, no atomics: fully deterministic.
// ---------------------------------------------------------------------------

namespace {

constexpr int NQ = 9;

// Forward basis permutation of one CNOT ring: CNOT(0,1), ..., CNOT(8,0)
__host__ __device__ constexpr int permP(int n) {
    int b[NQ] = {};
    for (int i = 0; i < NQ; ++i) b[i] = (n >> i) & 1;
    for (int i = 0; i < NQ; ++i) b[(i + 1) % NQ] ^= b[i];
    int r = 0;
    for (int i = 0; i < NQ; ++i) r |= b[i] << i;
    return r;
}
__host__ __device__ constexpr int invP(int y) {
    for (int n = 0; n < 512; ++n)
        if (permP(n) == y) return n;
    return 0;
}
// bit i of P(P(n)) == parity(n & rowPP(i))
__host__ __device__ constexpr int rowPP(int i) {
    int r = 0;
    for (int j = 0; j < NQ; ++j) {
        int y = permP(permP(1 << j));
        r |= ((y >> i) & 1) << j;
    }
    return r;
}
__host__ __device__ constexpr int cpop(int x) {
    int c = 0;
    while (x) { x &= x - 1; ++c; }
    return c;
}

constexpr int MAXT = 16;

struct TermTab {
    int   rmask[4];         // R_i: theta-support of filter i
    int   amask[4];         // A_i: w1 qubits entering filter i
    int   nt[4];            // surviving term count
    int   smask[4][MAXT];   // M_T: theta-sin mask (subset of R_i)
    int   tsub[4][MAXT];    // T:   w1-sin subset (subset of A_i)
    float sign[4][MAXT];
    bool  ok;
};

__host__ __device__ constexpr TermTab buildTerms() {
    TermTab T{};
    T.ok = true;
    int M[NQ] = {};
    for (int q = 0; q < NQ; ++q) M[q] = invP(1 << q);
    for (int i = 0; i < 4; ++i) {
        const int R = rowPP(i);
        T.rmask[i] = R;
        int A = 0;
        for (int q = 0; q < NQ; ++q)
            if (cpop(M[q] & R) & 1) A |= 1 << q;
        T.amask[i] = A;
        int n = 0;
        for (int s = 0; s < (1 << NQ); ++s) {
            if (s & ~A) continue;
            int xm = 0;
            for (int q = 0; q < NQ; ++q)
                if ((s >> q) & 1) xm ^= M[q];
            if (xm & ~R) continue;          // any X outside R -> <X>=0, dies
            const int e = cpop(s) + cpop(xm);
            if (e & 1) T.ok = false;        // surviving phase must be real
            if (n >= MAXT) { T.ok = false; continue; }
            T.smask[i][n] = xm;
            T.tsub[i][n]  = s;
            T.sign[i][n]  = ((e & 3) == 0) ? 1.f : -1.f;   // i^e = +/-1
            ++n;
        }
        T.nt[i] = n;
    }
    return T;
}

// Compile-time validation of the derivation invariants.
static_assert(buildTerms().ok, "Pauli term table invariant violated");
static_assert(buildTerms().nt[0] >= 1 && buildTerms().nt[1] >= 1 &&
              buildTerms().nt[2] >= 1 && buildTerms().nt[3] >= 1,
              "each filter must have at least the identity term");

__global__ void __launch_bounds__(16)
quanv_kernel(const float* __restrict__ x, const float* __restrict__ qw,
             float* __restrict__ out) {
    constexpr int C = 3, H = 28, W = 28, HO = 26, WO = 26;
    constexpr TermTab TT = buildTerms();

    const int patch = blockIdx.x * 16 + threadIdx.x;
    if (patch >= 4 * HO * WO) return;

    const int xo = patch % WO;
    const int yo = (patch / WO) % HO;
    const int b  = patch / (WO * HO);

    // ---- Issue all 27 input loads up front (hide DRAM/L2 latency) ----
    float xv[C][NQ];
#pragma unroll
    for (int ch = 0; ch < C; ++ch) {
        const float* xp = x + ((b * C + ch) * H + yo) * W + xo;
#pragma unroll
        for (int j = 0; j < NQ; ++j)
            xv[ch][j] = __ldg(xp + (j / 3) * W + (j % 3));
    }

    // ---- w0 and w1 trig (uniform; overlaps load latency) ----
    float w0[NQ], cw[NQ], sw[NQ];
#pragma unroll
    for (int q = 0; q < NQ; ++q) {
        w0[q] = __ldg(qw + q);
        __sincosf(__ldg(qw + NQ + q), &sw[q], &cw[q]);
    }

    // ---- Per-term coefficients from w1 (compile-time masks fold) ----
    float coef[4][MAXT];
#pragma unroll
    for (int i = 0; i < 4; ++i) {
#pragma unroll
        for (int t = 0; t < MAXT; ++t) {
            if (t < TT.nt[i]) {
                float p = TT.sign[i][t];
#pragma unroll
                for (int q = 0; q < NQ; ++q) {
                    if ((TT.amask[i] >> q) & 1)
                        p *= ((TT.tsub[i][t] >> q) & 1) ? sw[q] : cw[q];
                }
                coef[i][t] = p;
            }
        }
    }

    // ---- Channel loop: 9 sincos + 16 monomials each ----
    float z[4] = {0.f, 0.f, 0.f, 0.f};
#pragma unroll
    for (int ch = 0; ch < C; ++ch) {
        float cth[NQ], sth[NQ];
#pragma unroll
        for (int j = 0; j < NQ; ++j)
            __sincosf(xv[ch][j] + w0[j], &sth[j], &cth[j]);

#pragma unroll
        for (int i = 0; i < 4; ++i) {
            float zi = 0.f;
#pragma unroll
            for (int t = 0; t < MAXT; ++t) {
                if (t < TT.nt[i]) {
                    float p = coef[i][t];
#pragma unroll
                    for (int j = 0; j < NQ; ++j) {
                        if ((TT.rmask[i] >> j) & 1)
                            p *= ((TT.smask[i][t] >> j) & 1) ? sth[j] : cth[j];
                    }
                    zi += p;
                }
            }
            z[i] += zi;
        }
    }

    const float inv3 = 1.f / 3.f;
#pragma unroll
    for (int f = 0; f < 4; ++f)
        out[((b * 4 + f) * HO + yo) * WO + xo] = z[f] * inv3;
}

}  // namespace

extern "C" void kernel_launch(void* const* d_in, const int* in_sizes, int n_in,
                              void* d_out, int out_size) {
    const float* x  = (const float*)d_in[0];   // (4,3,28,28) float32
    const float* qw = (const float*)d_in[1];   // (2,9) float32
    float* out = (float*)d_out;                // (4,4,26,26) float32

    // One thread per patch: 4*26*26 = 2704 = 169 blocks * 16 threads (exact).
    quanv_kernel<<<169, 16>>>(x, qw, out);
}